// round 1
// baseline (speedup 1.0000x reference)
#include <cuda_runtime.h>

// Problem dims
#define B_   256
#define T_   32
#define IN_  2312
#define H_   1024
#define OUT_ 10

// LIF constants (norse defaults per reference)
#define DT_TAUMEM 0.05f   // DT * TAU_MEM_INV
#define DT_TAUSYN 0.2f    // DT * TAU_SYN_INV

// Scratch / state (device globals; no allocation allowed)
__device__ float g_inp1[T_ * B_ * H_];   // precomputed x_t @ W1^T + b1, layout [t][b][h]
__device__ float g_v1[B_ * H_], g_i1[B_ * H_];
__device__ float g_v2[B_ * H_], g_i2[B_ * H_];
__device__ float g_s1[B_ * H_], g_s2[B_ * H_];
__device__ float g_vo[B_ * OUT_], g_io[B_ * OUT_];

__device__ __forceinline__ void lif_update(float& v, float& cur, float inp, float& s) {
    float vd = v + DT_TAUMEM * (cur - v);     // v + dt/tau_mem * (-v + i)
    float id = cur - DT_TAUSYN * cur;         // i - dt/tau_syn * i
    s = (vd - 1.0f) > 0.0f ? 1.0f : 0.0f;
    v = (1.0f - s) * vd;                      // reset to 0 on spike
    cur = id + inp;
}

// ---------------------------------------------------------------------------
// Init: zero all state + output
// ---------------------------------------------------------------------------
__global__ void init_kernel(float* __restrict__ out) {
    int idx = blockIdx.x * blockDim.x + threadIdx.x;
    if (idx < B_ * H_) {
        g_v1[idx] = 0.f; g_i1[idx] = 0.f;
        g_v2[idx] = 0.f; g_i2[idx] = 0.f;
    }
    if (idx < B_ * OUT_) {
        g_vo[idx] = 0.f; g_io[idx] = 0.f;
        out[idx] = 0.f;
    }
}

// ---------------------------------------------------------------------------
// GEMM1: g_inp1[t*B+b][h] = x[b*T+t][:] . W1[h][:] + b1[h]
// M = B*T = 8192 (m = b*32 + t), N = 1024, K = 2312
// Tiled fp32 SIMT GEMM: BM=BN=64, BK=16, 256 threads, 4x4 per thread
// ---------------------------------------------------------------------------
__global__ void __launch_bounds__(256) gemm1_kernel(
    const float* __restrict__ x, const float* __restrict__ W1,
    const float* __restrict__ b1)
{
    __shared__ float As[16][65];
    __shared__ float Bs[16][65];

    int tid = threadIdx.x;
    int lc = tid & 15;    // k within tile (coalesced along K)
    int lr = tid >> 4;    // 0..15

    int m0 = blockIdx.y * 64;
    int n0 = blockIdx.x * 64;
    int ty = tid >> 4;    // 0..15 -> 4 rows each
    int tx = tid & 15;    // 0..15 -> 4 cols each

    float acc[4][4];
#pragma unroll
    for (int i = 0; i < 4; i++)
#pragma unroll
        for (int j = 0; j < 4; j++) acc[i][j] = 0.f;

    for (int k0 = 0; k0 < IN_; k0 += 16) {
        int kk = k0 + lc;
        bool kin = kk < IN_;
#pragma unroll
        for (int i = 0; i < 4; i++) {
            int m = m0 + lr + 16 * i;                 // m = b*32 + t (x row)
            As[lc][lr + 16 * i] = kin ? x[(long)m * IN_ + kk] : 0.f;
            Bs[lc][lr + 16 * i] = kin ? W1[(long)(n0 + lr + 16 * i) * IN_ + kk] : 0.f;
        }
        __syncthreads();
#pragma unroll
        for (int k = 0; k < 16; k++) {
            float a[4], bb[4];
#pragma unroll
            for (int i = 0; i < 4; i++) { a[i] = As[k][ty * 4 + i]; bb[i] = Bs[k][tx * 4 + i]; }
#pragma unroll
            for (int i = 0; i < 4; i++)
#pragma unroll
                for (int j = 0; j < 4; j++) acc[i][j] = fmaf(a[i], bb[j], acc[i][j]);
        }
        __syncthreads();
    }

#pragma unroll
    for (int i = 0; i < 4; i++) {
        int m = m0 + ty * 4 + i;
        int b = m >> 5;            // m = b*32 + t
        int t = m & 31;
        long orow = ((long)t * B_ + b) * H_;
#pragma unroll
        for (int j = 0; j < 4; j++) {
            int h = n0 + tx * 4 + j;
            g_inp1[orow + h] = acc[i][j] + b1[h];
        }
    }
}

// ---------------------------------------------------------------------------
// Per-step layer-1 LIF update (elementwise over B*H)
// ---------------------------------------------------------------------------
__global__ void spike1_kernel(int t) {
    int idx = blockIdx.x * blockDim.x + threadIdx.x;   // grid covers B_*H_ exactly
    float v = g_v1[idx], cur = g_i1[idx], s;
    lif_update(v, cur, g_inp1[(long)t * (B_ * H_) + idx], s);
    g_v1[idx] = v; g_i1[idx] = cur; g_s1[idx] = s;
}

// ---------------------------------------------------------------------------
// Per-step GEMM2 + fused LIF2: inp2 = s1 @ W2^T + b2  -> s2
// M=256 (batch), N=1024 (h), K=1024 (j). BM=32, BN=64, BK=32, 256 threads.
// ---------------------------------------------------------------------------
#define G2_BM 32
#define G2_BN 64
#define G2_BK 32
__global__ void __launch_bounds__(256) g2_kernel(
    const float* __restrict__ W2, const float* __restrict__ b2)
{
    __shared__ float Ss[G2_BK][G2_BM + 2];
    __shared__ float Ws[G2_BK][G2_BN + 1];

    int tid = threadIdx.x;
    int lc = tid & 31;   // k within tile
    int lr = tid >> 5;   // 0..7

    int m0 = blockIdx.y * G2_BM;
    int n0 = blockIdx.x * G2_BN;
    int tx = tid & 15;
    int ty = tid >> 4;   // 0..15 -> 2 rows each

    float acc[2][4];
#pragma unroll
    for (int i = 0; i < 2; i++)
#pragma unroll
        for (int j = 0; j < 4; j++) acc[i][j] = 0.f;

    for (int k0 = 0; k0 < H_; k0 += G2_BK) {
#pragma unroll
        for (int i = 0; i < 4; i++)
            Ss[lc][lr + 8 * i] = g_s1[(m0 + lr + 8 * i) * H_ + k0 + lc];
#pragma unroll
        for (int i = 0; i < 8; i++)
            Ws[lc][lr + 8 * i] = W2[(long)(n0 + lr + 8 * i) * H_ + k0 + lc];
        __syncthreads();
#pragma unroll
        for (int k = 0; k < G2_BK; k++) {
            float a0 = Ss[k][ty * 2 + 0];
            float a1 = Ss[k][ty * 2 + 1];
            float bb[4];
#pragma unroll
            for (int j = 0; j < 4; j++) bb[j] = Ws[k][tx * 4 + j];
#pragma unroll
            for (int j = 0; j < 4; j++) {
                acc[0][j] = fmaf(a0, bb[j], acc[0][j]);
                acc[1][j] = fmaf(a1, bb[j], acc[1][j]);
            }
        }
        __syncthreads();
    }

    // Fused LIF-2 epilogue (each (b,h) owned by exactly one thread)
#pragma unroll
    for (int i = 0; i < 2; i++) {
        int b = m0 + ty * 2 + i;
#pragma unroll
        for (int j = 0; j < 4; j++) {
            int h = n0 + tx * 4 + j;
            int idx = b * H_ + h;
            float v = g_v2[idx], cur = g_i2[idx], s;
            lif_update(v, cur, acc[i][j] + b2[h], s);
            g_v2[idx] = v; g_i2[idx] = cur; g_s2[idx] = s;
        }
    }
}

// ---------------------------------------------------------------------------
// Per-step output GEMV + LIF-out + rate accumulation.
// One block per batch; 10 warps, one per output neuron.
// ---------------------------------------------------------------------------
__global__ void __launch_bounds__(320) out_kernel(
    const float* __restrict__ Wout, const float* __restrict__ bout,
    float* __restrict__ out)
{
    __shared__ float s2s[H_];
    int b = blockIdx.x;
    int tid = threadIdx.x;
    for (int j = tid; j < H_; j += 320) s2s[j] = g_s2[b * H_ + j];
    __syncthreads();

    int w = tid >> 5, lane = tid & 31;
    if (w < OUT_) {
        float sum = 0.f;
        for (int j = lane; j < H_; j += 32)
            sum = fmaf(s2s[j], Wout[w * H_ + j], sum);
#pragma unroll
        for (int off = 16; off; off >>= 1)
            sum += __shfl_xor_sync(0xffffffff, sum, off);
        if (lane == 0) {
            int idx = b * OUT_ + w;
            float v = g_vo[idx], cur = g_io[idx], s;
            lif_update(v, cur, sum + bout[w], s);
            g_vo[idx] = v; g_io[idx] = cur;
            out[idx] += s;
        }
    }
}

// ---------------------------------------------------------------------------
extern "C" void kernel_launch(void* const* d_in, const int* in_sizes, int n_in,
                              void* d_out, int out_size)
{
    const float* x    = (const float*)d_in[0];
    const float* W1   = (const float*)d_in[1];
    const float* b1   = (const float*)d_in[2];
    const float* W2   = (const float*)d_in[3];
    const float* b2   = (const float*)d_in[4];
    const float* Wout = (const float*)d_in[5];
    const float* bout = (const float*)d_in[6];
    float* out = (float*)d_out;

    init_kernel<<<(B_ * H_ + 255) / 256, 256>>>(out);

    // Time-parallel input GEMM: all T steps at once
    gemm1_kernel<<<dim3(H_ / 64, (B_ * T_) / 64), 256>>>(x, W1, b1);

    // Sequential recurrence over T
    for (int t = 0; t < T_; t++) {
        spike1_kernel<<<(B_ * H_) / 256, 256>>>(t);
        g2_kernel<<<dim3(H_ / G2_BN, B_ / G2_BM), 256>>>(W2, b2);
        out_kernel<<<B_, 320>>>(Wout, bout, out);
    }
}

// round 2
// speedup vs baseline: 1.6297x; 1.6297x over previous
#include <cuda_runtime.h>

// Problem dims
#define B_   256
#define T_   32
#define IN_  2312
#define H_   1024
#define OUT_ 10
#define BH   (B_ * H_)

// LIF constants
#define DT_TAUMEM 0.05f
#define DT_TAUSYN 0.2f

// Device-global scratch / state
__device__ float g_inp1[T_ * BH];        // x_t @ W1^T + b1, [t][b][h]
__device__ float g_v1[BH], g_i1[BH];
__device__ float g_v2[BH], g_i2[BH];
__device__ float g_s1[BH];
__device__ float g_part[4 * BH];         // split-K partials for GEMM2
__device__ float g_vo[B_ * OUT_], g_io[B_ * OUT_];

__device__ __forceinline__ void lif_update(float& v, float& cur, float inp, float& s) {
    float vd = v + DT_TAUMEM * (cur - v);
    float id = cur - DT_TAUSYN * cur;
    s = (vd - 1.0f) > 0.0f ? 1.0f : 0.0f;
    v = (1.0f - s) * vd;
    cur = id + inp;
}

// ---------------------------------------------------------------------------
__global__ void init_kernel(float* __restrict__ out) {
    int idx = blockIdx.x * blockDim.x + threadIdx.x;
    if (idx < BH) {
        g_v1[idx] = 0.f; g_i1[idx] = 0.f;
        g_v2[idx] = 0.f; g_i2[idx] = 0.f;
    }
    if (idx < B_ * OUT_) {
        g_vo[idx] = 0.f; g_io[idx] = 0.f;
        out[idx] = 0.f;
    }
}

// ---------------------------------------------------------------------------
// GEMM1: g_inp1[t][b][h] = x[b,t,:] . W1[h,:] + b1[h]
// M = B*T = 8192 (m = b*32+t), N = 1024, K = 2312. 64x64 tile, 4x4/thread,
// float4 smem reads -> FMA-bound inner loop.
// ---------------------------------------------------------------------------
__global__ void __launch_bounds__(256) gemm1_kernel(
    const float* __restrict__ x, const float* __restrict__ W1,
    const float* __restrict__ b1)
{
    __shared__ float As[16][68];
    __shared__ float Bs[16][68];

    int tid = threadIdx.x;
    int lc = tid & 15;    // k within slab
    int lr = tid >> 4;    // 0..15

    int m0 = blockIdx.y * 64;
    int n0 = blockIdx.x * 64;
    int ty = tid >> 4;    // 0..15
    int tx = tid & 15;    // 0..15

    float acc[4][4];
#pragma unroll
    for (int i = 0; i < 4; i++)
#pragma unroll
        for (int j = 0; j < 4; j++) acc[i][j] = 0.f;

    for (int k0 = 0; k0 < IN_; k0 += 16) {
        int kk = k0 + lc;
        bool kin = kk < IN_;
#pragma unroll
        for (int i = 0; i < 4; i++) {
            int m = m0 + lr + 16 * i;
            As[lc][lr + 16 * i] = kin ? x[(long)m * IN_ + kk] : 0.f;
            Bs[lc][lr + 16 * i] = kin ? W1[(long)(n0 + lr + 16 * i) * IN_ + kk] : 0.f;
        }
        __syncthreads();
#pragma unroll
        for (int k = 0; k < 16; k++) {
            float4 a  = *(const float4*)&As[k][ty * 4];
            float4 bb = *(const float4*)&Bs[k][tx * 4];
            acc[0][0] = fmaf(a.x, bb.x, acc[0][0]);
            acc[0][1] = fmaf(a.x, bb.y, acc[0][1]);
            acc[0][2] = fmaf(a.x, bb.z, acc[0][2]);
            acc[0][3] = fmaf(a.x, bb.w, acc[0][3]);
            acc[1][0] = fmaf(a.y, bb.x, acc[1][0]);
            acc[1][1] = fmaf(a.y, bb.y, acc[1][1]);
            acc[1][2] = fmaf(a.y, bb.z, acc[1][2]);
            acc[1][3] = fmaf(a.y, bb.w, acc[1][3]);
            acc[2][0] = fmaf(a.z, bb.x, acc[2][0]);
            acc[2][1] = fmaf(a.z, bb.y, acc[2][1]);
            acc[2][2] = fmaf(a.z, bb.z, acc[2][2]);
            acc[2][3] = fmaf(a.z, bb.w, acc[2][3]);
            acc[3][0] = fmaf(a.w, bb.x, acc[3][0]);
            acc[3][1] = fmaf(a.w, bb.y, acc[3][1]);
            acc[3][2] = fmaf(a.w, bb.z, acc[3][2]);
            acc[3][3] = fmaf(a.w, bb.w, acc[3][3]);
        }
        __syncthreads();
    }

#pragma unroll
    for (int i = 0; i < 4; i++) {
        int m = m0 + ty * 4 + i;
        int b = m >> 5;
        int t = m & 31;
        long orow = ((long)t * B_ + b) * H_;
#pragma unroll
        for (int j = 0; j < 4; j++) {
            int h = n0 + tx * 4 + j;
            g_inp1[orow + h] = acc[i][j] + b1[h];
        }
    }
}

// ---------------------------------------------------------------------------
// Layer-1 LIF, standalone (used only for t=0)
// ---------------------------------------------------------------------------
__global__ void spike1_kernel(int t) {
    int idx = blockIdx.x * blockDim.x + threadIdx.x;
    float v = g_v1[idx], cur = g_i1[idx], s;
    lif_update(v, cur, g_inp1[(long)t * BH + idx], s);
    g_v1[idx] = v; g_i1[idx] = cur; g_s1[idx] = s;
}

// ---------------------------------------------------------------------------
// GEMM2 split-K partial: g_part[z][b][h] = sum_{k in chunk z} s1[b][k]*W2[h][k]
// M=256, N=1024, K per block = 256. Tiles 32x64, 256 threads, 2x4 per thread.
// Grid (16, 8, 4) = 512 blocks.
// ---------------------------------------------------------------------------
#define G2_BM 32
#define G2_BN 64
#define G2_BK 32
#define G2_KC 256
__global__ void __launch_bounds__(256) g2_partial_kernel(const float* __restrict__ W2)
{
    __shared__ float Ss[G2_BK][G2_BM + 2];   // pad 34: float2-aligned
    __shared__ float Ws[G2_BK][G2_BN + 4];   // pad 68: float4-aligned

    int tid = threadIdx.x;
    int lc = tid & 31;
    int lr = tid >> 5;

    int m0 = blockIdx.y * G2_BM;
    int n0 = blockIdx.x * G2_BN;
    int kbase = blockIdx.z * G2_KC;
    int tx = tid & 15;
    int ty = tid >> 4;

    float acc[2][4];
#pragma unroll
    for (int i = 0; i < 2; i++)
#pragma unroll
        for (int j = 0; j < 4; j++) acc[i][j] = 0.f;

    for (int k0 = kbase; k0 < kbase + G2_KC; k0 += G2_BK) {
#pragma unroll
        for (int i = 0; i < 4; i++)
            Ss[lc][lr + 8 * i] = g_s1[(m0 + lr + 8 * i) * H_ + k0 + lc];
#pragma unroll
        for (int i = 0; i < 8; i++)
            Ws[lc][lr + 8 * i] = W2[(long)(n0 + lr + 8 * i) * H_ + k0 + lc];
        __syncthreads();
#pragma unroll
        for (int k = 0; k < G2_BK; k++) {
            float2 a  = *(const float2*)&Ss[k][ty * 2];
            float4 bb = *(const float4*)&Ws[k][tx * 4];
            acc[0][0] = fmaf(a.x, bb.x, acc[0][0]);
            acc[0][1] = fmaf(a.x, bb.y, acc[0][1]);
            acc[0][2] = fmaf(a.x, bb.z, acc[0][2]);
            acc[0][3] = fmaf(a.x, bb.w, acc[0][3]);
            acc[1][0] = fmaf(a.y, bb.x, acc[1][0]);
            acc[1][1] = fmaf(a.y, bb.y, acc[1][1]);
            acc[1][2] = fmaf(a.y, bb.z, acc[1][2]);
            acc[1][3] = fmaf(a.y, bb.w, acc[1][3]);
        }
        __syncthreads();
    }

    long base = (long)blockIdx.z * BH;
#pragma unroll
    for (int i = 0; i < 2; i++) {
        int b = m0 + ty * 2 + i;
        *(float4*)&g_part[base + (long)b * H_ + n0 + tx * 4] =
            make_float4(acc[i][0], acc[i][1], acc[i][2], acc[i][3]);
    }
}

// ---------------------------------------------------------------------------
// Fused per-step tail: reduce split-K partials + LIF2 -> s2 (smem only),
// output GEMV + LIF-out + rate accumulate, then layer-1 LIF for step t+1.
// One block per batch element, 512 threads.
// ---------------------------------------------------------------------------
__global__ void __launch_bounds__(512) fused_tail_kernel(
    const float* __restrict__ Wout, const float* __restrict__ b2,
    const float* __restrict__ bout, float* __restrict__ out, int t)
{
    __shared__ float s2s[H_];
    int b = blockIdx.x;
    int tid = threadIdx.x;

    // Reduce partials + bias -> LIF2 -> s2 (stays in smem)
#pragma unroll
    for (int rep = 0; rep < 2; rep++) {
        int h = tid + rep * 512;
        int idx = b * H_ + h;
        float sum = g_part[idx] + g_part[BH + idx] + g_part[2 * BH + idx]
                  + g_part[3 * BH + idx] + b2[h];
        float v = g_v2[idx], cur = g_i2[idx], s;
        lif_update(v, cur, sum, s);
        g_v2[idx] = v; g_i2[idx] = cur;
        s2s[h] = s;
    }
    __syncthreads();

    // Output GEMV (warp w -> output neuron w) + LIF-out + accumulate
    int w = tid >> 5, lane = tid & 31;
    if (w < OUT_) {
        float sum = 0.f;
#pragma unroll 8
        for (int j = lane; j < H_; j += 32)
            sum = fmaf(s2s[j], __ldg(&Wout[w * H_ + j]), sum);
#pragma unroll
        for (int off = 16; off; off >>= 1)
            sum += __shfl_xor_sync(0xffffffff, sum, off);
        if (lane == 0) {
            int idx = b * OUT_ + w;
            float v = g_vo[idx], cur = g_io[idx], s;
            lif_update(v, cur, sum + bout[w], s);
            g_vo[idx] = v; g_io[idx] = cur;
            out[idx] += s;
        }
    }

    // Layer-1 LIF for the NEXT step (independent of everything above)
    if (t + 1 < T_) {
#pragma unroll
        for (int rep = 0; rep < 2; rep++) {
            int h = tid + rep * 512;
            int idx = b * H_ + h;
            float v = g_v1[idx], cur = g_i1[idx], s;
            lif_update(v, cur, g_inp1[(long)(t + 1) * BH + idx], s);
            g_v1[idx] = v; g_i1[idx] = cur; g_s1[idx] = s;
        }
    }
}

// ---------------------------------------------------------------------------
extern "C" void kernel_launch(void* const* d_in, const int* in_sizes, int n_in,
                              void* d_out, int out_size)
{
    const float* x    = (const float*)d_in[0];
    const float* W1   = (const float*)d_in[1];
    const float* b1   = (const float*)d_in[2];
    const float* W2   = (const float*)d_in[3];
    const float* b2   = (const float*)d_in[4];
    const float* Wout = (const float*)d_in[5];
    const float* bout = (const float*)d_in[6];
    float* out = (float*)d_out;

    init_kernel<<<BH / 256, 256>>>(out);

    // Time-parallel input GEMM
    gemm1_kernel<<<dim3(H_ / 64, (B_ * T_) / 64), 256>>>(x, W1, b1);

    // First-step layer-1 LIF
    spike1_kernel<<<BH / 256, 256>>>(0);

    // Recurrence: 2 kernels per step
    for (int t = 0; t < T_; t++) {
        g2_partial_kernel<<<dim3(H_ / G2_BN, B_ / G2_BM, 4), 256>>>(W2);
        fused_tail_kernel<<<B_, 512>>>(Wout, b2, bout, out, t);
    }
}

// round 3
// speedup vs baseline: 2.3893x; 1.4661x over previous
#include <cuda_runtime.h>

// Problem dims
#define B_   256
#define T_   32
#define IN_  2312
#define H_   1024
#define OUT_ 10
#define BH   (B_ * H_)

// LIF constants
#define DT_TAUMEM 0.05f
#define DT_TAUSYN 0.2f

#define KSPL 8                      // split-K factor for GEMM2

// Device-global scratch / state
__device__ float g_inp1[T_ * BH];   // x_t @ W1^T + b1, [t][b][h]
__device__ float g_v1[BH], g_i1[BH];
__device__ float g_v2[BH], g_i2[BH];
__device__ float g_s1[BH];
__device__ float g_part[KSPL * BH];
__device__ float g_vo[B_ * OUT_], g_io[B_ * OUT_];

__device__ __forceinline__ void lif_update(float& v, float& cur, float inp, float& s) {
    float vd = v + DT_TAUMEM * (cur - v);
    float id = cur - DT_TAUSYN * cur;
    s = (vd - 1.0f) > 0.0f ? 1.0f : 0.0f;
    v = (1.0f - s) * vd;
    cur = id + inp;
}

// ---- packed f32x2 helpers (FFMA2 path) ------------------------------------
__device__ __forceinline__ unsigned long long dup2(float x) {
    unsigned long long r;
    asm("mov.b64 %0, {%1, %1};" : "=l"(r) : "f"(x));
    return r;
}
__device__ __forceinline__ unsigned long long pk2(float x, float y) {
    unsigned long long r;
    asm("mov.b64 %0, {%1, %2};" : "=l"(r) : "f"(x), "f"(y));
    return r;
}
__device__ __forceinline__ void fma2(unsigned long long& d,
                                     unsigned long long a, unsigned long long b) {
    asm("fma.rn.f32x2 %0, %1, %2, %0;" : "+l"(d) : "l"(a), "l"(b));
}
__device__ __forceinline__ float2 up2(unsigned long long v) {
    float2 f;
    asm("mov.b64 {%0, %1}, %2;" : "=f"(f.x), "=f"(f.y) : "l"(v));
    return f;
}

// ---------------------------------------------------------------------------
__global__ void init_kernel(float* __restrict__ out) {
    int idx = blockIdx.x * blockDim.x + threadIdx.x;
    if (idx < BH) {
        g_v1[idx] = 0.f; g_i1[idx] = 0.f;
        g_v2[idx] = 0.f; g_i2[idx] = 0.f;
    }
    if (idx < B_ * OUT_) {
        g_vo[idx] = 0.f; g_io[idx] = 0.f;
        out[idx] = 0.f;
    }
}

// ---------------------------------------------------------------------------
// GEMM1: g_inp1[t][b][h] = x[m=b*32+t,:] . W1[h,:] + b1[h]
// M=8192, N=1024, K=2312. Tile 128x128, BK=8, 256 thr, 8x8/thread, FFMA2.
// ---------------------------------------------------------------------------
#define G1_BM 128
#define G1_BN 128
#define G1_BK 8
#define G1_PAD 132
__global__ void __launch_bounds__(256) gemm1_kernel(
    const float* __restrict__ x, const float* __restrict__ W1,
    const float* __restrict__ b1)
{
    __shared__ float As[2][G1_BK][G1_PAD];
    __shared__ float Bs[2][G1_BK][G1_PAD];

    int tid = threadIdx.x;
    int m0 = blockIdx.y * G1_BM;
    int n0 = blockIdx.x * G1_BN;

    int lrow = tid >> 1;            // 0..127
    int lk4  = (tid & 1) * 4;       // 0 or 4
    const float* aptr = x  + (long)(m0 + lrow) * IN_ + lk4;
    const float* bptr = W1 + (long)(n0 + lrow) * IN_ + lk4;

    int tx = tid & 15;              // col group
    int ty = tid >> 4;              // row group

    unsigned long long acc[8][4];
#pragma unroll
    for (int r = 0; r < 8; r++)
#pragma unroll
        for (int c = 0; c < 4; c++) acc[r][c] = 0ULL;

    // prologue: tile 0
    float4 ra = *(const float4*)aptr;
    float4 rb = *(const float4*)bptr;
#pragma unroll
    for (int i = 0; i < 4; i++) {
        As[0][lk4 + i][lrow] = ((const float*)&ra)[i];
        Bs[0][lk4 + i][lrow] = ((const float*)&rb)[i];
    }
    __syncthreads();

    const int nIter = IN_ / G1_BK;  // 289
    for (int it = 0; it < nIter; it++) {
        int cur = it & 1, nxt = cur ^ 1;
        if (it + 1 < nIter) {
            ra = *(const float4*)(aptr + (long)(it + 1) * G1_BK);
            rb = *(const float4*)(bptr + (long)(it + 1) * G1_BK);
        }
#pragma unroll
        for (int k = 0; k < G1_BK; k++) {
            float4 a0 = *(const float4*)&As[cur][k][ty * 4];
            float4 a1 = *(const float4*)&As[cur][k][ty * 4 + 64];
            float4 b0 = *(const float4*)&Bs[cur][k][tx * 4];
            float4 b1 = *(const float4*)&Bs[cur][k][tx * 4 + 64];
            unsigned long long ap[8], bp[4];
            ap[0] = dup2(a0.x); ap[1] = dup2(a0.y); ap[2] = dup2(a0.z); ap[3] = dup2(a0.w);
            ap[4] = dup2(a1.x); ap[5] = dup2(a1.y); ap[6] = dup2(a1.z); ap[7] = dup2(a1.w);
            bp[0] = pk2(b0.x, b0.y); bp[1] = pk2(b0.z, b0.w);
            bp[2] = pk2(b1.x, b1.y); bp[3] = pk2(b1.z, b1.w);
#pragma unroll
            for (int r = 0; r < 8; r++)
#pragma unroll
                for (int c = 0; c < 4; c++) fma2(acc[r][c], ap[r], bp[c]);
        }
        if (it + 1 < nIter) {
#pragma unroll
            for (int i = 0; i < 4; i++) {
                As[nxt][lk4 + i][lrow] = ((const float*)&ra)[i];
                Bs[nxt][lk4 + i][lrow] = ((const float*)&rb)[i];
            }
        }
        __syncthreads();
    }

    // epilogue: add bias, scatter to [t][b][h]
#pragma unroll
    for (int r = 0; r < 8; r++) {
        int m = m0 + ty * 4 + (r & 3) + (r >> 2) * 64;
        int b = m >> 5;
        int t = m & 31;
        long orow = ((long)t * B_ + b) * H_;
#pragma unroll
        for (int c = 0; c < 4; c++) {
            int h = n0 + tx * 4 + (c & 1) * 2 + (c >> 1) * 64;
            float2 v = up2(acc[r][c]);
            g_inp1[orow + h]     = v.x + b1[h];
            g_inp1[orow + h + 1] = v.y + b1[h + 1];
        }
    }
}

// ---------------------------------------------------------------------------
// Layer-1 LIF, standalone (t=0 only)
// ---------------------------------------------------------------------------
__global__ void spike1_kernel(int t) {
    int idx = blockIdx.x * blockDim.x + threadIdx.x;
    float v = g_v1[idx], cur = g_i1[idx], s;
    lif_update(v, cur, g_inp1[(long)t * BH + idx], s);
    g_v1[idx] = v; g_i1[idx] = cur; g_s1[idx] = s;
}

// ---------------------------------------------------------------------------
// GEMM2 split-K partial with FFMA2.
// M=256, N=1024, K=1024, KSPL=8 (KC=128). Tile 64x128, BK=16, 256 thr,
// 4x8 per thread. Grid (8, 4, 8) = 256 blocks.
// ---------------------------------------------------------------------------
#define G2_BM 64
#define G2_BN 128
#define G2_BK 16
#define G2_KC (H_ / KSPL)    // 128
#define G2_PADA 68
#define G2_PADB 132
__global__ void __launch_bounds__(256) g2_partial_kernel(const float* __restrict__ W2)
{
    __shared__ float Ss[2][G2_BK][G2_PADA];
    __shared__ float Ws[2][G2_BK][G2_PADB];

    int tid = threadIdx.x;
    int m0 = blockIdx.y * G2_BM;
    int n0 = blockIdx.x * G2_BN;
    int kbase = blockIdx.z * G2_KC;

    int lrow = tid >> 2;          // 0..63
    int lk4  = (tid & 3) * 4;     // 0,4,8,12
    const float* aptr = g_s1 + (long)(m0 + lrow) * H_ + kbase + lk4;
    const float* bptr0 = W2 + (long)(n0 + lrow) * H_ + kbase + lk4;
    const float* bptr1 = W2 + (long)(n0 + lrow + 64) * H_ + kbase + lk4;

    int tx = tid & 15;
    int ty = tid >> 4;

    unsigned long long acc[4][4];
#pragma unroll
    for (int r = 0; r < 4; r++)
#pragma unroll
        for (int c = 0; c < 4; c++) acc[r][c] = 0ULL;

    float4 ra = *(const float4*)aptr;
    float4 rb0 = *(const float4*)bptr0;
    float4 rb1 = *(const float4*)bptr1;
#pragma unroll
    for (int i = 0; i < 4; i++) {
        Ss[0][lk4 + i][lrow] = ((const float*)&ra)[i];
        Ws[0][lk4 + i][lrow] = ((const float*)&rb0)[i];
        Ws[0][lk4 + i][lrow + 64] = ((const float*)&rb1)[i];
    }
    __syncthreads();

    const int nIter = G2_KC / G2_BK;   // 8
#pragma unroll 1
    for (int it = 0; it < nIter; it++) {
        int cur = it & 1, nxt = cur ^ 1;
        if (it + 1 < nIter) {
            ra  = *(const float4*)(aptr  + (it + 1) * G2_BK);
            rb0 = *(const float4*)(bptr0 + (it + 1) * G2_BK);
            rb1 = *(const float4*)(bptr1 + (it + 1) * G2_BK);
        }
#pragma unroll
        for (int k = 0; k < G2_BK; k++) {
            float4 a0 = *(const float4*)&Ss[cur][k][ty * 4];
            float4 b0 = *(const float4*)&Ws[cur][k][tx * 4];
            float4 b1 = *(const float4*)&Ws[cur][k][tx * 4 + 64];
            unsigned long long ap[4], bp[4];
            ap[0] = dup2(a0.x); ap[1] = dup2(a0.y); ap[2] = dup2(a0.z); ap[3] = dup2(a0.w);
            bp[0] = pk2(b0.x, b0.y); bp[1] = pk2(b0.z, b0.w);
            bp[2] = pk2(b1.x, b1.y); bp[3] = pk2(b1.z, b1.w);
#pragma unroll
            for (int r = 0; r < 4; r++)
#pragma unroll
                for (int c = 0; c < 4; c++) fma2(acc[r][c], ap[r], bp[c]);
        }
        if (it + 1 < nIter) {
#pragma unroll
            for (int i = 0; i < 4; i++) {
                Ss[nxt][lk4 + i][lrow] = ((const float*)&ra)[i];
                Ws[nxt][lk4 + i][lrow] = ((const float*)&rb0)[i];
                Ws[nxt][lk4 + i][lrow + 64] = ((const float*)&rb1)[i];
            }
        }
        __syncthreads();
    }

    long base = (long)blockIdx.z * BH;
#pragma unroll
    for (int r = 0; r < 4; r++) {
        int b = m0 + ty * 4 + r;
        long row = base + (long)b * H_;
#pragma unroll
        for (int c = 0; c < 4; c++) {
            int h = n0 + tx * 4 + (c & 1) * 2 + (c >> 1) * 64;
            float2 v = up2(acc[r][c]);
            g_part[row + h]     = v.x;
            g_part[row + h + 1] = v.y;
        }
    }
}

// ---------------------------------------------------------------------------
// Fused per-step tail: reduce split-K partials + LIF2 -> s2 (smem),
// output GEMV + LIF-out + rate accumulate, then layer-1 LIF for step t+1.
// ---------------------------------------------------------------------------
__global__ void __launch_bounds__(512) fused_tail_kernel(
    const float* __restrict__ Wout, const float* __restrict__ b2,
    const float* __restrict__ bout, float* __restrict__ out, int t)
{
    __shared__ float s2s[H_];
    int b = blockIdx.x;
    int tid = threadIdx.x;

#pragma unroll
    for (int rep = 0; rep < 2; rep++) {
        int h = tid + rep * 512;
        int idx = b * H_ + h;
        float sum = b2[h];
#pragma unroll
        for (int z = 0; z < KSPL; z++) sum += g_part[(long)z * BH + idx];
        float v = g_v2[idx], cur = g_i2[idx], s;
        lif_update(v, cur, sum, s);
        g_v2[idx] = v; g_i2[idx] = cur;
        s2s[h] = s;
    }
    __syncthreads();

    int w = tid >> 5, lane = tid & 31;
    if (w < OUT_) {
        float sum = 0.f;
#pragma unroll 8
        for (int j = lane; j < H_; j += 32)
            sum = fmaf(s2s[j], __ldg(&Wout[w * H_ + j]), sum);
#pragma unroll
        for (int off = 16; off; off >>= 1)
            sum += __shfl_xor_sync(0xffffffff, sum, off);
        if (lane == 0) {
            int idx = b * OUT_ + w;
            float v = g_vo[idx], cur = g_io[idx], s;
            lif_update(v, cur, sum + bout[w], s);
            g_vo[idx] = v; g_io[idx] = cur;
            out[idx] += s;
        }
    }

    if (t + 1 < T_) {
#pragma unroll
        for (int rep = 0; rep < 2; rep++) {
            int h = tid + rep * 512;
            int idx = b * H_ + h;
            float v = g_v1[idx], cur = g_i1[idx], s;
            lif_update(v, cur, g_inp1[(long)(t + 1) * BH + idx], s);
            g_v1[idx] = v; g_i1[idx] = cur; g_s1[idx] = s;
        }
    }
}

// ---------------------------------------------------------------------------
extern "C" void kernel_launch(void* const* d_in, const int* in_sizes, int n_in,
                              void* d_out, int out_size)
{
    const float* x    = (const float*)d_in[0];
    const float* W1   = (const float*)d_in[1];
    const float* b1   = (const float*)d_in[2];
    const float* W2   = (const float*)d_in[3];
    const float* b2   = (const float*)d_in[4];
    const float* Wout = (const float*)d_in[5];
    const float* bout = (const float*)d_in[6];
    float* out = (float*)d_out;

    init_kernel<<<BH / 256, 256>>>(out);

    // Time-parallel input GEMM (FFMA2)
    gemm1_kernel<<<dim3(G1_BN == 128 ? H_ / 128 : 0 + H_ / G1_BN, (B_ * T_) / G1_BM), 256>>>(x, W1, b1);

    // First-step layer-1 LIF
    spike1_kernel<<<BH / 256, 256>>>(0);

    // Recurrence: 2 kernels per step
    for (int t = 0; t < T_; t++) {
        g2_partial_kernel<<<dim3(H_ / G2_BN, B_ / G2_BM, KSPL), 256>>>(W2);
        fused_tail_kernel<<<B_, 512>>>(Wout, b2, bout, out, t);
    }
}